// round 16
// baseline (speedup 1.0000x reference)
#include <cuda_runtime.h>
#include <cuda_fp16.h>
#include <math.h>
#include <stdint.h>

// ---------------- problem constants ----------------
#define L_SEQ   4096
#define DMODEL  1024
#define DINNER  2048
#define EDIM    (2*DINNER)   // 4096
#define BATCH   2
#define NFFT    8192
#define NHALF   (NFFT/2)     // 4096
#define NTHR    1024         // fftk block size
#define NCHUNK  4            // GEMM1/convfft pipeline chunks

#define SKW(i)  ((i) + ((i) >> 4))
#define SKWN    (NFFT + NFFT/16)       // 8704 float2 (8192 buffer, fftk)
#define SKWN4   (4096 + 4096/16)       // 4352 float2 (4096 buffer, convfft)

extern __shared__ char s4_smem[];

// ---------------- scratch (device globals; allocation-free launch) ----------------
__device__ __half g_xzH[(unsigned long long)BATCH * EDIM * L_SEQ];     // [b][e][l] fp16
__device__ __half g_yH [(unsigned long long)BATCH * DINNER * L_SEQ];   // [b][h][l] fp16
__device__ __half g_hsH [(unsigned long long)BATCH * L_SEQ * DMODEL];
__device__ __half g_WinH[(unsigned long long)EDIM * DMODEL];
__device__ __half g_WoutH[(unsigned long long)DMODEL * DINNER];
__device__ float2 g_Hf[(unsigned long long)DINNER * NFFT];
__device__ float2 g_tw[NHALF];                                         // e^{-2pi i k/8192}

// ---------------- f32 -> f16 bulk convert ----------------
__global__ void __launch_bounds__(256) f2h_kernel(const float* __restrict__ src,
                                                  __half* __restrict__ dst,
                                                  long long n4)
{
    long long i = ((long long)blockIdx.x * 256 + threadIdx.x);
    if (i < n4) {
        float4 v = *(const float4*)(src + i * 4);
        __half2 h01 = __floats2half2_rn(v.x, v.y);
        __half2 h23 = __floats2half2_rn(v.z, v.w);
        *(uint2*)(dst + i * 4) = make_uint2(*(uint32_t*)&h01, *(uint32_t*)&h23);
    }
}

// ---------------- mma / ldmatrix / cp.async helpers ----------------
__device__ __forceinline__ void mma_f16(float* d, const uint32_t* a, const uint32_t* b) {
    asm volatile(
        "mma.sync.aligned.m16n8k16.row.col.f32.f16.f16.f32 "
        "{%0,%1,%2,%3}, {%4,%5,%6,%7}, {%8,%9}, {%0,%1,%2,%3};"
        : "+f"(d[0]), "+f"(d[1]), "+f"(d[2]), "+f"(d[3])
        : "r"(a[0]), "r"(a[1]), "r"(a[2]), "r"(a[3]), "r"(b[0]), "r"(b[1]));
}
__device__ __forceinline__ void ldsm_x4(uint32_t* r, uint32_t saddr) {
    asm volatile("ldmatrix.sync.aligned.m8n8.x4.shared.b16 {%0,%1,%2,%3}, [%4];"
                 : "=r"(r[0]), "=r"(r[1]), "=r"(r[2]), "=r"(r[3]) : "r"(saddr));
}
__device__ __forceinline__ void ldsm_x4_t(uint32_t* r, uint32_t saddr) {
    asm volatile("ldmatrix.sync.aligned.m8n8.x4.trans.shared.b16 {%0,%1,%2,%3}, [%4];"
                 : "=r"(r[0]), "=r"(r[1]), "=r"(r[2]), "=r"(r[3]) : "r"(saddr));
}
__device__ __forceinline__ void cp16(uint32_t saddr, const void* gaddr) {
    asm volatile("cp.async.cg.shared.global [%0], [%1], 16;" :: "r"(saddr), "l"(gaddr));
}
__device__ __forceinline__ void cp_commit() {
    asm volatile("cp.async.commit_group;" ::: "memory");
}
template<int N>
__device__ __forceinline__ void cp_wait() {
    asm volatile("cp.async.wait_group %0;" :: "n"(N) : "memory");
}

#define GPITCH 40
#define APITCH 136
#define STAGES 3

// ============ GEMM1 (NT) chunk: two e-bands of 512 rows each ========
// xzH[m][n] = sum_k W_in[m][k] * hs[n][k]; m from bands, n = l.
__global__ void __launch_bounds__(256) gemm_mma_h(const __half* __restrict__ A,
                                                  const __half* __restrict__ B,
                                                  __half* __restrict__ C,
                                                  int mBand0, int mBand1)
{
    __shared__ __half As[STAGES][128][GPITCH];
    __shared__ __half Bs[STAGES][128][GPITCH];

    B += (size_t)blockIdx.z * L_SEQ * DMODEL;
    C += (size_t)blockIdx.z * EDIM * L_SEQ;
    const int by = blockIdx.y;
    const int m0 = (by < 4) ? (mBand0 + by * 128) : (mBand1 + (by - 4) * 128);
    const int n0 = blockIdx.x * 128;

    const int tid  = threadIdx.x;
    const int wid  = tid >> 5;
    const int lane = tid & 31;
    const int wm   = (wid >> 2) * 64;
    const int wn   = (wid & 3) * 32;
    const int g    = lane >> 2;
    const int t    = lane & 3;

    const int aRow = (lane & 15);
    const int aCol = (lane >> 4) * 8;
    const int bRow = (lane & 7) + ((lane >> 4) << 3);
    const int bCol = ((lane >> 3) & 1) * 8;

    float acc[4][4][4];
    #pragma unroll
    for (int mi = 0; mi < 4; ++mi)
        #pragma unroll
        for (int ni = 0; ni < 4; ++ni)
            #pragma unroll
            for (int r = 0; r < 4; ++r) acc[mi][ni][r] = 0.f;

    const int nch = DMODEL >> 5;

    auto issue = [&](int st, int c) {
        const int k0 = c << 5;
        #pragma unroll
        for (int p = 0; p < 2; ++p) {
            int lin = p * 256 + tid;
            int row = lin >> 2;
            int grp = lin & 3;
            uint32_t sa = (uint32_t)__cvta_generic_to_shared(&As[st][row][grp * 8]);
            cp16(sa, A + (size_t)(m0 + row) * DMODEL + k0 + grp * 8);
            uint32_t sb = (uint32_t)__cvta_generic_to_shared(&Bs[st][row][grp * 8]);
            cp16(sb, B + (size_t)(n0 + row) * DMODEL + k0 + grp * 8);
        }
        cp_commit();
    };

    issue(0, 0);
    issue(1, 1);

    for (int c = 0; c < nch; ++c) {
        cp_wait<STAGES - 2>();
        __syncthreads();

        if (c + STAGES - 1 < nch)
            issue((c + STAGES - 1) % STAGES, c + STAGES - 1);

        const int buf = c % STAGES;
        #pragma unroll
        for (int ks = 0; ks < 2; ++ks) {
            const int kk = ks * 16;
            uint32_t af[4][4], bf[4][4];
            #pragma unroll
            for (int mi = 0; mi < 4; ++mi) {
                uint32_t sa = (uint32_t)__cvta_generic_to_shared(
                    &As[buf][wm + mi * 16 + aRow][kk + aCol]);
                ldsm_x4(af[mi], sa);
            }
            #pragma unroll
            for (int np = 0; np < 2; ++np) {
                uint32_t sb = (uint32_t)__cvta_generic_to_shared(
                    &Bs[buf][wn + np * 16 + bRow][kk + bCol]);
                ldsm_x4(bf[np * 2], sb);
                bf[np * 2 + 1][0] = bf[np * 2][2];
                bf[np * 2 + 1][1] = bf[np * 2][3];
            }
            #pragma unroll
            for (int mi = 0; mi < 4; ++mi)
                #pragma unroll
                for (int ni = 0; ni < 4; ++ni)
                    mma_f16(acc[mi][ni], af[mi], bf[ni]);
        }
    }

    #pragma unroll
    for (int mi = 0; mi < 4; ++mi) {
        int r0 = m0 + wm + mi * 16 + g;
        #pragma unroll
        for (int ni = 0; ni < 4; ++ni) {
            int cc = n0 + wn + ni * 8 + t * 2;
            *(__half2*)(C + (size_t)r0 * L_SEQ + cc) =
                __floats2half2_rn(acc[mi][ni][0], acc[mi][ni][1]);
            *(__half2*)(C + (size_t)(r0 + 8) * L_SEQ + cc) =
                __floats2half2_rn(acc[mi][ni][2], acc[mi][ni][3]);
        }
    }
}

// ================= GEMM2 (NN): out[b][l][d] = sum_h y[b][h][l] * W_out[d][h] =======
__global__ void __launch_bounds__(256) gemm2_nn(const __half* __restrict__ Y,
                                                const __half* __restrict__ W,
                                                float* __restrict__ C)
{
    __shared__ __half As[STAGES][32][APITCH];
    __shared__ __half Bs[STAGES][128][GPITCH];

    Y += (size_t)blockIdx.z * DINNER * L_SEQ;
    C += (size_t)blockIdx.z * L_SEQ * DMODEL;
    const int m0 = blockIdx.y * 128;
    const int n0 = blockIdx.x * 128;

    const int tid  = threadIdx.x;
    const int wid  = tid >> 5;
    const int lane = tid & 31;
    const int wm   = (wid >> 2) * 64;
    const int wn   = (wid & 3) * 32;
    const int g    = lane >> 2;
    const int t    = lane & 3;

    const int kOff = (lane & 7) + ((lane >> 4) << 3);
    const int mOff = ((lane >> 3) & 1) * 8;
    const int bRow = (lane & 7) + ((lane >> 4) << 3);
    const int bCol = ((lane >> 3) & 1) * 8;

    float acc[4][4][4];
    #pragma unroll
    for (int mi = 0; mi < 4; ++mi)
        #pragma unroll
        for (int ni = 0; ni < 4; ++ni)
            #pragma unroll
            for (int r = 0; r < 4; ++r) acc[mi][ni][r] = 0.f;

    const int nch = DINNER >> 5;

    auto issue = [&](int st, int c) {
        const int k0 = c << 5;
        #pragma unroll
        for (int p = 0; p < 2; ++p) {
            int lin = p * 256 + tid;
            int arow = lin >> 4;
            int agrp = lin & 15;
            uint32_t sa = (uint32_t)__cvta_generic_to_shared(&As[st][arow][agrp * 8]);
            cp16(sa, Y + (size_t)(k0 + arow) * L_SEQ + m0 + agrp * 8);
            int brow = lin >> 2;
            int bgrp = lin & 3;
            uint32_t sb = (uint32_t)__cvta_generic_to_shared(&Bs[st][brow][bgrp * 8]);
            cp16(sb, W + (size_t)(n0 + brow) * DINNER + k0 + bgrp * 8);
        }
        cp_commit();
    };

    issue(0, 0);
    issue(1, 1);

    for (int c = 0; c < nch; ++c) {
        cp_wait<STAGES - 2>();
        __syncthreads();

        if (c + STAGES - 1 < nch)
            issue((c + STAGES - 1) % STAGES, c + STAGES - 1);

        const int buf = c % STAGES;
        #pragma unroll
        for (int ks = 0; ks < 2; ++ks) {
            const int kk = ks * 16;
            uint32_t af[4][4], bf[4][4];
            #pragma unroll
            for (int mi = 0; mi < 4; ++mi) {
                uint32_t sa = (uint32_t)__cvta_generic_to_shared(
                    &As[buf][kk + kOff][wm + mi * 16 + mOff]);
                ldsm_x4_t(af[mi], sa);
            }
            #pragma unroll
            for (int np = 0; np < 2; ++np) {
                uint32_t sb = (uint32_t)__cvta_generic_to_shared(
                    &Bs[buf][wn + np * 16 + bRow][kk + bCol]);
                ldsm_x4(bf[np * 2], sb);
                bf[np * 2 + 1][0] = bf[np * 2][2];
                bf[np * 2 + 1][1] = bf[np * 2][3];
            }
            #pragma unroll
            for (int mi = 0; mi < 4; ++mi)
                #pragma unroll
                for (int ni = 0; ni < 4; ++ni)
                    mma_f16(acc[mi][ni], af[mi], bf[ni]);
        }
    }

    #pragma unroll
    for (int mi = 0; mi < 4; ++mi) {
        int r0 = m0 + wm + mi * 16 + g;
        #pragma unroll
        for (int ni = 0; ni < 4; ++ni) {
            int cc = n0 + wn + ni * 8 + t * 2;
            *(float2*)(C + (size_t)r0 * DMODEL + cc)       = make_float2(acc[mi][ni][0], acc[mi][ni][1]);
            *(float2*)(C + (size_t)(r0 + 8) * DMODEL + cc) = make_float2(acc[mi][ni][2], acc[mi][ni][3]);
        }
    }
}

// ---------------- twiddle table ----------------
__global__ void twiddle_kernel() {
    int k = blockIdx.x * blockDim.x + threadIdx.x;
    if (k < NHALF) {
        float s, c;
        sincospif(2.0f * (float)k / (float)NFFT, &s, &c);
        g_tw[k] = make_float2(c, -s);
    }
}

// ---------------- complex helpers ----------------
__device__ __forceinline__ float2 cmul(float2 a, float2 b) {
    return make_float2(fmaf(a.x, b.x, -a.y * b.y), fmaf(a.x, b.y, a.y * b.x));
}
__device__ __forceinline__ float2 cadd(float2 a, float2 b) { return make_float2(a.x + b.x, a.y + b.y); }
__device__ __forceinline__ float2 csub(float2 a, float2 b) { return make_float2(a.x - b.x, a.y - b.y); }
__device__ __forceinline__ float silu_f(float x) { return x / (1.0f + __expf(-x)); }

// ---------------- FFT 8192: Stockham radix-8 (4 stages) + radix-2, 1024 thr --------
__device__ float2* fft8192_r8(float2* src, float2* dst, const float2* __restrict__ tw,
                              float sgn, int tid, bool padded, bool halfOut)
{
    const float RH = 0.70710678118654752f;

    int s = 1;
    #pragma unroll 1
    for (int st = 0; st < 4; ++st) {
        const int sm1 = s - 1;
        {
            int i  = tid;
            int q  = i & sm1;
            int ps = i - q;

            float2 a0 = src[SKW(i)];
            float2 a1 = src[SKW(i + 1024)];
            float2 a2 = src[SKW(i + 2048)];
            float2 a3 = src[SKW(i + 3072)];

            float2 E0, E1, E2, E3, O0, O1, O2, O3;
            if (padded && st == 0) {
                float2 m2 = make_float2(sgn * a2.y, -sgn * a2.x);
                float2 m3 = make_float2(sgn * a3.y, -sgn * a3.x);
                E0 = cadd(a0, a2); E2 = csub(a0, a2);
                E1 = cadd(a0, m2); E3 = csub(a0, m2);
                O0 = cadd(a1, a3); O2 = csub(a1, a3);
                O1 = cadd(a1, m3); O3 = csub(a1, m3);
            } else {
                float2 a4 = src[SKW(i + 4096)];
                float2 a5 = src[SKW(i + 5120)];
                float2 a6 = src[SKW(i + 6144)];
                float2 a7 = src[SKW(i + 7168)];
                float2 t0 = cadd(a0, a4), t1 = csub(a0, a4);
                float2 t2 = cadd(a2, a6), t3 = csub(a2, a6);
                float2 m3e = make_float2(sgn * t3.y, -sgn * t3.x);
                E0 = cadd(t0, t2); E2 = csub(t0, t2);
                E1 = cadd(t1, m3e); E3 = csub(t1, m3e);
                float2 u0 = cadd(a1, a5), u1 = csub(a1, a5);
                float2 u2 = cadd(a3, a7), u3 = csub(a3, a7);
                float2 m3o = make_float2(sgn * u3.y, -sgn * u3.x);
                O0 = cadd(u0, u2); O2 = csub(u0, u2);
                O1 = cadd(u1, m3o); O3 = csub(u1, m3o);
            }

            float2 W1O = make_float2(RH * (O1.x + sgn * O1.y), RH * (O1.y - sgn * O1.x));
            float2 W2O = make_float2(sgn * O2.y, -sgn * O2.x);
            float2 W3O = make_float2(RH * (sgn * O3.y - O3.x), -RH * (O3.y + sgn * O3.x));

            float2 X0 = cadd(E0, O0),  X4 = csub(E0, O0);
            float2 X1 = cadd(E1, W1O), X5 = csub(E1, W1O);
            float2 X2 = cadd(E2, W2O), X6 = csub(E2, W2O);
            float2 X3 = cadd(E3, W3O), X7 = csub(E3, W3O);

            float2 w1 = tw[ps];     w1.y *= sgn;
            float2 w2 = tw[2 * ps]; w2.y *= sgn;
            float2 w4 = tw[4 * ps]; w4.y *= sgn;
            float2 w3 = cmul(w1, w2);
            float2 w5 = cmul(w1, w4);
            float2 w6 = cmul(w2, w4);
            float2 w7 = cmul(w3, w4);

            int o = q + 8 * ps;
            dst[SKW(o)]         = X0;
            dst[SKW(o + s)]     = cmul(X1, w1);
            dst[SKW(o + 2 * s)] = cmul(X2, w2);
            dst[SKW(o + 3 * s)] = cmul(X3, w3);
            dst[SKW(o + 4 * s)] = cmul(X4, w4);
            dst[SKW(o + 5 * s)] = cmul(X5, w5);
            dst[SKW(o + 6 * s)] = cmul(X6, w6);
            dst[SKW(o + 7 * s)] = cmul(X7, w7);
        }
        __syncthreads();
        float2* t = src; src = dst; dst = t;
        s <<= 3;
    }

    #pragma unroll
    for (int r = 0; r < 4; ++r) {
        int i = tid + r * NTHR;
        float2 a = src[SKW(i)];
        float2 b = src[SKW(i + NHALF)];
        dst[SKW(i)] = cadd(a, b);
        if (!halfOut) dst[SKW(i + NHALF)] = csub(a, b);
    }
    __syncthreads();
    return dst;
}

// ---------------- FFT 4096: Stockham radix-8, 4 stages, 512 thr --------------------
__device__ float2* fft4096_r8(float2* src, float2* dst, const float2* __restrict__ tw,
                              float sgn, int tid, bool padded, bool halfOut)
{
    const float RH = 0.70710678118654752f;

    int s = 1;
    #pragma unroll 1
    for (int st = 0; st < 4; ++st) {
        const int sm1 = s - 1;
        {
            int i  = tid;
            int q  = i & sm1;
            int ps = i - q;

            float2 a0 = src[SKW(i)];
            float2 a1 = src[SKW(i + 512)];
            float2 a2 = src[SKW(i + 1024)];
            float2 a3 = src[SKW(i + 1536)];

            float2 E0, E1, E2, E3, O0, O1, O2, O3;
            if (padded && st == 0) {
                float2 m2 = make_float2(sgn * a2.y, -sgn * a2.x);
                float2 m3 = make_float2(sgn * a3.y, -sgn * a3.x);
                E0 = cadd(a0, a2); E2 = csub(a0, a2);
                E1 = cadd(a0, m2); E3 = csub(a0, m2);
                O0 = cadd(a1, a3); O2 = csub(a1, a3);
                O1 = cadd(a1, m3); O3 = csub(a1, m3);
            } else {
                float2 a4 = src[SKW(i + 2048)];
                float2 a5 = src[SKW(i + 2560)];
                float2 a6 = src[SKW(i + 3072)];
                float2 a7 = src[SKW(i + 3584)];
                float2 t0 = cadd(a0, a4), t1 = csub(a0, a4);
                float2 t2 = cadd(a2, a6), t3 = csub(a2, a6);
                float2 m3e = make_float2(sgn * t3.y, -sgn * t3.x);
                E0 = cadd(t0, t2); E2 = csub(t0, t2);
                E1 = cadd(t1, m3e); E3 = csub(t1, m3e);
                float2 u0 = cadd(a1, a5), u1 = csub(a1, a5);
                float2 u2 = cadd(a3, a7), u3 = csub(a3, a7);
                float2 m3o = make_float2(sgn * u3.y, -sgn * u3.x);
                O0 = cadd(u0, u2); O2 = csub(u0, u2);
                O1 = cadd(u1, m3o); O3 = csub(u1, m3o);
            }

            float2 W1O = make_float2(RH * (O1.x + sgn * O1.y), RH * (O1.y - sgn * O1.x));
            float2 W2O = make_float2(sgn * O2.y, -sgn * O2.x);
            float2 W3O = make_float2(RH * (sgn * O3.y - O3.x), -RH * (O3.y + sgn * O3.x));

            float2 X0 = cadd(E0, O0),  X4 = csub(E0, O0);
            float2 X1 = cadd(E1, W1O), X5 = csub(E1, W1O);
            float2 X2 = cadd(E2, W2O), X6 = csub(E2, W2O);
            float2 X3 = cadd(E3, W3O), X7 = csub(E3, W3O);

            float2 w1 = tw[ps];     w1.y *= sgn;
            float2 w2 = tw[2 * ps]; w2.y *= sgn;
            float2 w4 = tw[4 * ps]; w4.y *= sgn;
            float2 w3 = cmul(w1, w2);

            int o = q + 8 * ps;
            dst[SKW(o)]         = X0;
            dst[SKW(o + s)]     = cmul(X1, w1);
            dst[SKW(o + 2 * s)] = cmul(X2, w2);
            dst[SKW(o + 3 * s)] = cmul(X3, w3);
            if (!(halfOut && st == 3)) {
                float2 w5 = cmul(w1, w4);
                float2 w6 = cmul(w2, w4);
                float2 w7 = cmul(w3, w4);
                dst[SKW(o + 4 * s)] = cmul(X4, w4);
                dst[SKW(o + 5 * s)] = cmul(X5, w5);
                dst[SKW(o + 6 * s)] = cmul(X6, w6);
                dst[SKW(o + 7 * s)] = cmul(X7, w7);
            }
        }
        __syncthreads();
        float2* t = src; src = dst; dst = t;
        s <<= 3;
    }
    return src;
}

// ---------------- kernel spectra: two real channels per 8192 FFT -------------------
#define SMEM_FFTK ((2 * SKWN + NHALF) * (int)sizeof(float2))
__global__ void __launch_bounds__(NTHR) fftk_kernel(const float* __restrict__ k_ssm)
{
    float2* buf0 = (float2*)s4_smem;
    float2* buf1 = buf0 + SKWN;
    float2* tws  = buf1 + SKWN;
    const int h0 = blockIdx.x * 2;
    const int tid = threadIdx.x;

    for (int i = tid; i < NHALF; i += NTHR) tws[i] = g_tw[i];
    const float* k0 = k_ssm + (size_t)h0 * L_SEQ;
    const float* k1 = k0 + L_SEQ;
    for (int l = tid; l < L_SEQ; l += NTHR)
        buf0[SKW(l)] = make_float2(k0[l], k1[l]);
    __syncthreads();

    float2* F = fft8192_r8(buf0, buf1, tws, 1.0f, tid, true, false);

    float2* H0 = g_Hf + (size_t)h0 * NFFT;
    float2* H1 = H0 + NFFT;
    for (int k = tid; k < NFFT; k += NTHR) {
        float2 Fk = F[SKW(k)];
        float2 Fn = F[SKW((NFFT - k) & (NFFT - 1))];
        H0[k] = make_float2(0.5f * (Fk.x + Fn.x), 0.5f * (Fk.y - Fn.y));
        float2 Bd = make_float2(Fk.x - Fn.x, Fk.y + Fn.y);
        H1[k] = make_float2(0.5f * Bd.y, -0.5f * Bd.x);
    }
}

// ------- fused conv chunk: conv4+SiLU -> rFFT(4096) conv -> D_skip -> *SiLU(z) -----
#define SMEM_CONV4 ((2 * SKWN4 + 2048 + 2048) * (int)sizeof(float2))
__global__ void __launch_bounds__(512, 2) convfft_kernel(const float* __restrict__ conv_w,
                                                         const float* __restrict__ conv_b,
                                                         const float* __restrict__ D_skip,
                                                         int hBase)
{
    float2* buf0 = (float2*)s4_smem;
    float2* buf1 = buf0 + SKWN4;
    float2* tws  = buf1 + SKWN4;      // 2048 entries: e^{-2pi i x/4096}
    float2* xs   = tws + 2048;

    const int bh  = blockIdx.x;
    const int h   = hBase + (bh >> 1);
    const int b   = bh & 1;
    const int tid = threadIdx.x;

    for (int j = tid; j < 2048; j += 512) tws[j] = g_tw[2 * j];

    const float w0 = conv_w[h * 4 + 0];
    const float w1 = conv_w[h * 4 + 1];
    const float w2 = conv_w[h * 4 + 2];
    const float w3 = conv_w[h * 4 + 3];
    const float cb = conv_b[h];

    const __half* gx = g_xzH + ((size_t)(b * EDIM) + h) * L_SEQ;

    for (int n = tid; n < 2048; n += 512) {
        int l0 = 2 * n;
        float x0  = __half2float(gx[l0]);
        float x1  = __half2float(gx[l0 + 1]);
        float a0 = fmaf(w3, x0, cb);
        float a1 = fmaf(w3, x1, cb);
        a1 = fmaf(w2, x0, a1);
        if (l0 >= 1) {
            float xm1 = __half2float(gx[l0 - 1]);
            a0 = fmaf(w2, xm1, a0); a1 = fmaf(w1, xm1, a1);
        }
        if (l0 >= 2) {
            float xm2 = __half2float(gx[l0 - 2]);
            a0 = fmaf(w1, xm2, a0); a1 = fmaf(w0, xm2, a1);
        }
        if (l0 >= 3) {
            float xm3 = __half2float(gx[l0 - 3]);
            a0 = fmaf(w0, xm3, a0);
        }
        float2 v = make_float2(silu_f(a0), silu_f(a1));
        xs[n]        = v;
        buf0[SKW(n)] = v;
    }
    for (int n = 2048 + tid; n < 4096; n += 512)
        buf0[SKW(n)] = make_float2(0.f, 0.f);
    __syncthreads();

    float2* Z = fft4096_r8(buf0, buf1, tws, 1.0f, tid, true, false);
    float2* W = (Z == buf0) ? buf1 : buf0;

    // pointwise, paired: thread handles k=n and k'=4096-n (n=0 -> 0 and 2048)
    const float2* __restrict__ Hrow = g_Hf + (size_t)h * NFFT;
    for (int n = tid; n < 2048; n += 512) {
        const int ka = n;
        const int kb = (n == 0) ? 2048 : 4096 - n;
        float2 Za = Z[SKW(ka)];
        float2 Zb = Z[SKW(kb)];
        float2 ta = g_tw[ka];
        float2 tb = (n == 0) ? g_tw[2048] : make_float2(-ta.x, ta.y);
        float2 Pa = (n == 0) ? Za : Zb;
        float2 Pb = (n == 0) ? Zb : Za;

        {
            float2 Zc = make_float2(Pa.x, -Pa.y);
            float2 Ze = make_float2(0.5f * (Za.x + Zc.x), 0.5f * (Za.y + Zc.y));
            float2 d  = make_float2(Za.x - Zc.x, Za.y - Zc.y);
            float2 Zo = make_float2(0.5f * d.y, -0.5f * d.x);
            float2 tZo = cmul(ta, Zo);
            float2 Xa = cadd(Ze, tZo);
            float2 Xb = csub(Ze, tZo);
            float2 Ya = cmul(Xa, Hrow[ka]);
            float2 Yb = cmul(Xb, Hrow[ka + 4096]);
            float2 Ye = make_float2(0.5f * (Ya.x + Yb.x), 0.5f * (Ya.y + Yb.y));
            float2 u  = make_float2(0.5f * (Ya.x - Yb.x), 0.5f * (Ya.y - Yb.y));
            float2 tc = make_float2(ta.x, -ta.y);
            float2 Yo = cmul(tc, u);
            W[SKW(ka)] = make_float2(Ye.x - Yo.y, Ye.y + Yo.x);
        }
        {
            float2 Zc = make_float2(Pb.x, -Pb.y);
            float2 Ze = make_float2(0.5f * (Zb.x + Zc.x), 0.5f * (Zb.y + Zc.y));
            float2 d  = make_float2(Zb.x - Zc.x, Zb.y - Zc.y);
            float2 Zo = make_float2(0.5f * d.y, -0.5f * d.x);
            float2 tZo = cmul(tb, Zo);
            float2 Xa = cadd(Ze, tZo);
            float2 Xb = csub(Ze, tZo);
            float2 Ya = cmul(Xa, Hrow[kb]);
            float2 Yb = cmul(Xb, Hrow[kb + 4096]);
            float2 Ye = make_float2(0.5f * (Ya.x + Yb.x), 0.5f * (Ya.y + Yb.y));
            float2 u  = make_float2(0.5f * (Ya.x - Yb.x), 0.5f * (Ya.y - Yb.y));
            float2 tc = make_float2(tb.x, -tb.y);
            float2 Yo = cmul(tc, u);
            W[SKW(kb)] = make_float2(Ye.x - Yo.y, Ye.y + Yo.x);
        }
    }
    __syncthreads();

    float2* other = (W == buf0) ? buf1 : buf0;
    float2* R = fft4096_r8(W, other, tws, -1.0f, tid, false, true);

    const float dsk = D_skip[h];
    const __half* gz = g_xzH + ((size_t)(b * EDIM) + DINNER + h) * L_SEQ;
    __half*       gy = g_yH + ((size_t)(b * DINNER) + h) * L_SEQ;
    const float invn = 1.0f / 4096.0f;
    for (int n = tid; n < 2048; n += 512) {
        float2 wv = R[SKW(n)];
        float2 xv = xs[n];
        __half2 zh = *(const __half2*)(gz + 2 * n);
        float z0 = __half2float(__low2half(zh));
        float z1 = __half2float(__high2half(zh));
        float y0 = fmaf(wv.x, invn, dsk * xv.x);
        float y1 = fmaf(wv.y, invn, dsk * xv.y);
        *(__half2*)(gy + 2 * n) = __floats2half2_rn(y0 * silu_f(z0), y1 * silu_f(z1));
    }
}

// ---------------- launch ----------------
extern "C" void kernel_launch(void* const* d_in, const int* in_sizes, int n_in,
                              void* d_out, int out_size)
{
    (void)in_sizes; (void)n_in; (void)out_size;
    const float* hs     = (const float*)d_in[0];
    const float* W_in   = (const float*)d_in[1];
    const float* conv_w = (const float*)d_in[2];
    const float* conv_b = (const float*)d_in[3];
    const float* k_ssm  = (const float*)d_in[4];
    const float* D_skip = (const float*)d_in[5];
    const float* W_out  = (const float*)d_in[6];
    float* out = (float*)d_out;

    cudaFuncSetAttribute(fftk_kernel,    cudaFuncAttributeMaxDynamicSharedMemorySize, SMEM_FFTK);
    cudaFuncSetAttribute(convfft_kernel, cudaFuncAttributeMaxDynamicSharedMemorySize, SMEM_CONV4);

    __half* xzH  = nullptr; cudaGetSymbolAddress((void**)&xzH, g_xzH);
    __half* hsH  = nullptr; cudaGetSymbolAddress((void**)&hsH, g_hsH);
    __half* winH = nullptr; cudaGetSymbolAddress((void**)&winH, g_WinH);
    __half* woutH= nullptr; cudaGetSymbolAddress((void**)&woutH, g_WoutH);
    __half* yH   = nullptr; cudaGetSymbolAddress((void**)&yH, g_yH);

    cudaStream_t sB;
    cudaStreamCreateWithFlags(&sB, cudaStreamNonBlocking);
    cudaEvent_t eFork, eJoin, eG[NCHUNK];
    cudaEventCreateWithFlags(&eFork, cudaEventDisableTiming);
    cudaEventCreateWithFlags(&eJoin, cudaEventDisableTiming);
    for (int i = 0; i < NCHUNK; ++i)
        cudaEventCreateWithFlags(&eG[i], cudaEventDisableTiming);

    cudaEventRecord(eFork, 0);
    cudaStreamWaitEvent(sB, eFork, 0);

    // ---- stream B: twiddle -> f2h(W_out) -> fftk ----
    twiddle_kernel<<<NHALF / 512, 512, 0, sB>>>();
    {
        long long n4 = (long long)DMODEL * DINNER / 4;
        f2h_kernel<<<(unsigned)((n4 + 255) / 256), 256, 0, sB>>>(W_out, woutH, n4);
    }
    fftk_kernel<<<DINNER / 2, NTHR, SMEM_FFTK, sB>>>(k_ssm);

    // ---- main stream: f2h(hs, W_in) -> GEMM1 chunks (events per chunk) ----
    {
        long long n4;
        n4 = (long long)BATCH * L_SEQ * DMODEL / 4;
        f2h_kernel<<<(unsigned)((n4 + 255) / 256), 256>>>(hs, hsH, n4);
        n4 = (long long)EDIM * DMODEL / 4;
        f2h_kernel<<<(unsigned)((n4 + 255) / 256), 256>>>(W_in, winH, n4);
    }
    for (int i = 0; i < NCHUNK; ++i) {
        gemm_mma_h<<<dim3(L_SEQ / 128, 8, BATCH), 256>>>(
            winH, hsH, xzH, 512 * i, DINNER + 512 * i);
        cudaEventRecord(eG[i], 0);
    }

    // ---- stream B: convfft chunks, each gated on its GEMM1 chunk ----
    for (int i = 0; i < NCHUNK; ++i) {
        cudaStreamWaitEvent(sB, eG[i], 0);
        convfft_kernel<<<2 * 512, 512, SMEM_CONV4, sB>>>(conv_w, conv_b, D_skip, 512 * i);
    }
    cudaEventRecord(eJoin, sB);

    // ---- main stream: GEMM2 after all convfft ----
    cudaStreamWaitEvent(0, eJoin, 0);
    gemm2_nn<<<dim3(DMODEL / 128, L_SEQ / 128, BATCH), 256>>>(yH, woutH, out);
    // stream/events intentionally not destroyed (stream-capture safe; host-side only)
}

// round 17
// speedup vs baseline: 1.0275x; 1.0275x over previous
#include <cuda_runtime.h>
#include <cuda_fp16.h>
#include <math.h>
#include <stdint.h>

// ---------------- problem constants ----------------
#define L_SEQ   4096
#define DMODEL  1024
#define DINNER  2048
#define EDIM    (2*DINNER)   // 4096
#define BATCH   2
#define NFFT    8192
#define NHALF   (NFFT/2)     // 4096
#define NTHR    1024         // fftk block size

#define SKW(i)  ((i) + ((i) >> 4))
#define SKWN    (NFFT + NFFT/16)       // 8704 float2 (8192 buffer, fftk)
#define SKWN4   (4096 + 4096/16)       // 4352 float2 (4096 buffer, convfft)

extern __shared__ char s4_smem[];

// ---------------- scratch (device globals; allocation-free launch) ----------------
__device__ __half g_xzH[(unsigned long long)BATCH * EDIM * L_SEQ];     // [b][e][l] fp16
__device__ __half g_yH [(unsigned long long)BATCH * DINNER * L_SEQ];   // [b][h][l] fp16
__device__ __half g_hsH [(unsigned long long)BATCH * L_SEQ * DMODEL];
__device__ __half g_WinH[(unsigned long long)EDIM * DMODEL];
__device__ __half g_WoutH[(unsigned long long)DMODEL * DINNER];
__device__ float2 g_Hf[(unsigned long long)DINNER * NFFT];
__device__ float2 g_tw[NHALF];                                         // e^{-2pi i k/8192}

// ---------------- f32 -> f16 bulk convert ----------------
__global__ void __launch_bounds__(256) f2h_kernel(const float* __restrict__ src,
                                                  __half* __restrict__ dst,
                                                  long long n4)
{
    long long i = ((long long)blockIdx.x * 256 + threadIdx.x);
    if (i < n4) {
        float4 v = *(const float4*)(src + i * 4);
        __half2 h01 = __floats2half2_rn(v.x, v.y);
        __half2 h23 = __floats2half2_rn(v.z, v.w);
        *(uint2*)(dst + i * 4) = make_uint2(*(uint32_t*)&h01, *(uint32_t*)&h23);
    }
}

// ---------------- mma / ldmatrix / cp.async helpers ----------------
__device__ __forceinline__ void mma_f16(float* d, const uint32_t* a, const uint32_t* b) {
    asm volatile(
        "mma.sync.aligned.m16n8k16.row.col.f32.f16.f16.f32 "
        "{%0,%1,%2,%3}, {%4,%5,%6,%7}, {%8,%9}, {%0,%1,%2,%3};"
        : "+f"(d[0]), "+f"(d[1]), "+f"(d[2]), "+f"(d[3])
        : "r"(a[0]), "r"(a[1]), "r"(a[2]), "r"(a[3]), "r"(b[0]), "r"(b[1]));
}
__device__ __forceinline__ void ldsm_x4(uint32_t* r, uint32_t saddr) {
    asm volatile("ldmatrix.sync.aligned.m8n8.x4.shared.b16 {%0,%1,%2,%3}, [%4];"
                 : "=r"(r[0]), "=r"(r[1]), "=r"(r[2]), "=r"(r[3]) : "r"(saddr));
}
__device__ __forceinline__ void ldsm_x4_t(uint32_t* r, uint32_t saddr) {
    asm volatile("ldmatrix.sync.aligned.m8n8.x4.trans.shared.b16 {%0,%1,%2,%3}, [%4];"
                 : "=r"(r[0]), "=r"(r[1]), "=r"(r[2]), "=r"(r[3]) : "r"(saddr));
}
__device__ __forceinline__ void cp16(uint32_t saddr, const void* gaddr) {
    asm volatile("cp.async.cg.shared.global [%0], [%1], 16;" :: "r"(saddr), "l"(gaddr));
}
__device__ __forceinline__ void cp_commit() {
    asm volatile("cp.async.commit_group;" ::: "memory");
}
template<int N>
__device__ __forceinline__ void cp_wait() {
    asm volatile("cp.async.wait_group %0;" :: "n"(N) : "memory");
}

#define GPITCH 40
#define APITCH 136
#define STAGES 3

// ============ GEMM1 (NT): xzH[m][n] = sum_k W_in[m][k] * hs[n][k], fp16 out ========
__global__ void __launch_bounds__(256) gemm_mma_h(const __half* __restrict__ A,
                                                  const __half* __restrict__ B,
                                                  __half* __restrict__ C,
                                                  int lda, int ldb, int ldc, int K,
                                                  long long aBatch, long long bBatch,
                                                  long long cBatch)
{
    __shared__ __half As[STAGES][128][GPITCH];
    __shared__ __half Bs[STAGES][128][GPITCH];

    A += (size_t)blockIdx.z * aBatch;
    B += (size_t)blockIdx.z * bBatch;
    C += (size_t)blockIdx.z * cBatch;
    const int m0 = blockIdx.y * 128;
    const int n0 = blockIdx.x * 128;

    const int tid  = threadIdx.x;
    const int wid  = tid >> 5;
    const int lane = tid & 31;
    const int wm   = (wid >> 2) * 64;
    const int wn   = (wid & 3) * 32;
    const int g    = lane >> 2;
    const int t    = lane & 3;

    const int aRow = (lane & 15);
    const int aCol = (lane >> 4) * 8;
    const int bRow = (lane & 7) + ((lane >> 4) << 3);
    const int bCol = ((lane >> 3) & 1) * 8;

    float acc[4][4][4];
    #pragma unroll
    for (int mi = 0; mi < 4; ++mi)
        #pragma unroll
        for (int ni = 0; ni < 4; ++ni)
            #pragma unroll
            for (int r = 0; r < 4; ++r) acc[mi][ni][r] = 0.f;

    const int nch = K >> 5;

    auto issue = [&](int st, int c) {
        const int k0 = c << 5;
        #pragma unroll
        for (int p = 0; p < 2; ++p) {
            int lin = p * 256 + tid;
            int row = lin >> 2;
            int grp = lin & 3;
            uint32_t sa = (uint32_t)__cvta_generic_to_shared(&As[st][row][grp * 8]);
            cp16(sa, A + (size_t)(m0 + row) * lda + k0 + grp * 8);
            uint32_t sb = (uint32_t)__cvta_generic_to_shared(&Bs[st][row][grp * 8]);
            cp16(sb, B + (size_t)(n0 + row) * ldb + k0 + grp * 8);
        }
        cp_commit();
    };

    issue(0, 0);
    issue(1, 1);

    for (int c = 0; c < nch; ++c) {
        cp_wait<STAGES - 2>();
        __syncthreads();

        if (c + STAGES - 1 < nch)
            issue((c + STAGES - 1) % STAGES, c + STAGES - 1);

        const int buf = c % STAGES;
        #pragma unroll
        for (int ks = 0; ks < 2; ++ks) {
            const int kk = ks * 16;
            uint32_t af[4][4], bf[4][4];
            #pragma unroll
            for (int mi = 0; mi < 4; ++mi) {
                uint32_t sa = (uint32_t)__cvta_generic_to_shared(
                    &As[buf][wm + mi * 16 + aRow][kk + aCol]);
                ldsm_x4(af[mi], sa);
            }
            #pragma unroll
            for (int np = 0; np < 2; ++np) {
                uint32_t sb = (uint32_t)__cvta_generic_to_shared(
                    &Bs[buf][wn + np * 16 + bRow][kk + bCol]);
                ldsm_x4(bf[np * 2], sb);
                bf[np * 2 + 1][0] = bf[np * 2][2];
                bf[np * 2 + 1][1] = bf[np * 2][3];
            }
            #pragma unroll
            for (int mi = 0; mi < 4; ++mi)
                #pragma unroll
                for (int ni = 0; ni < 4; ++ni)
                    mma_f16(acc[mi][ni], af[mi], bf[ni]);
        }
    }

    #pragma unroll
    for (int mi = 0; mi < 4; ++mi) {
        int r0 = m0 + wm + mi * 16 + g;
        #pragma unroll
        for (int ni = 0; ni < 4; ++ni) {
            int cc = n0 + wn + ni * 8 + t * 2;
            *(__half2*)(C + (size_t)r0 * ldc + cc) =
                __floats2half2_rn(acc[mi][ni][0], acc[mi][ni][1]);
            *(__half2*)(C + (size_t)(r0 + 8) * ldc + cc) =
                __floats2half2_rn(acc[mi][ni][2], acc[mi][ni][3]);
        }
    }
}

// ================= GEMM2 (NN): out[b][l][d] = sum_h y[b][h][l] * W_out[d][h] =======
__global__ void __launch_bounds__(256) gemm2_nn(const __half* __restrict__ Y,
                                                const __half* __restrict__ W,
                                                float* __restrict__ C)
{
    __shared__ __half As[STAGES][32][APITCH];
    __shared__ __half Bs[STAGES][128][GPITCH];

    Y += (size_t)blockIdx.z * DINNER * L_SEQ;
    C += (size_t)blockIdx.z * L_SEQ * DMODEL;
    const int m0 = blockIdx.y * 128;
    const int n0 = blockIdx.x * 128;

    const int tid  = threadIdx.x;
    const int wid  = tid >> 5;
    const int lane = tid & 31;
    const int wm   = (wid >> 2) * 64;
    const int wn   = (wid & 3) * 32;
    const int g    = lane >> 2;
    const int t    = lane & 3;

    const int kOff = (lane & 7) + ((lane >> 4) << 3);
    const int mOff = ((lane >> 3) & 1) * 8;
    const int bRow = (lane & 7) + ((lane >> 4) << 3);
    const int bCol = ((lane >> 3) & 1) * 8;

    float acc[4][4][4];
    #pragma unroll
    for (int mi = 0; mi < 4; ++mi)
        #pragma unroll
        for (int ni = 0; ni < 4; ++ni)
            #pragma unroll
            for (int r = 0; r < 4; ++r) acc[mi][ni][r] = 0.f;

    const int nch = DINNER >> 5;

    auto issue = [&](int st, int c) {
        const int k0 = c << 5;
        #pragma unroll
        for (int p = 0; p < 2; ++p) {
            int lin = p * 256 + tid;
            int arow = lin >> 4;
            int agrp = lin & 15;
            uint32_t sa = (uint32_t)__cvta_generic_to_shared(&As[st][arow][agrp * 8]);
            cp16(sa, Y + (size_t)(k0 + arow) * L_SEQ + m0 + agrp * 8);
            int brow = lin >> 2;
            int bgrp = lin & 3;
            uint32_t sb = (uint32_t)__cvta_generic_to_shared(&Bs[st][brow][bgrp * 8]);
            cp16(sb, W + (size_t)(n0 + brow) * DINNER + k0 + bgrp * 8);
        }
        cp_commit();
    };

    issue(0, 0);
    issue(1, 1);

    for (int c = 0; c < nch; ++c) {
        cp_wait<STAGES - 2>();
        __syncthreads();

        if (c + STAGES - 1 < nch)
            issue((c + STAGES - 1) % STAGES, c + STAGES - 1);

        const int buf = c % STAGES;
        #pragma unroll
        for (int ks = 0; ks < 2; ++ks) {
            const int kk = ks * 16;
            uint32_t af[4][4], bf[4][4];
            #pragma unroll
            for (int mi = 0; mi < 4; ++mi) {
                uint32_t sa = (uint32_t)__cvta_generic_to_shared(
                    &As[buf][kk + kOff][wm + mi * 16 + mOff]);
                ldsm_x4_t(af[mi], sa);
            }
            #pragma unroll
            for (int np = 0; np < 2; ++np) {
                uint32_t sb = (uint32_t)__cvta_generic_to_shared(
                    &Bs[buf][wn + np * 16 + bRow][kk + bCol]);
                ldsm_x4(bf[np * 2], sb);
                bf[np * 2 + 1][0] = bf[np * 2][2];
                bf[np * 2 + 1][1] = bf[np * 2][3];
            }
            #pragma unroll
            for (int mi = 0; mi < 4; ++mi)
                #pragma unroll
                for (int ni = 0; ni < 4; ++ni)
                    mma_f16(acc[mi][ni], af[mi], bf[ni]);
        }
    }

    #pragma unroll
    for (int mi = 0; mi < 4; ++mi) {
        int r0 = m0 + wm + mi * 16 + g;
        #pragma unroll
        for (int ni = 0; ni < 4; ++ni) {
            int cc = n0 + wn + ni * 8 + t * 2;
            *(float2*)(C + (size_t)r0 * DMODEL + cc)       = make_float2(acc[mi][ni][0], acc[mi][ni][1]);
            *(float2*)(C + (size_t)(r0 + 8) * DMODEL + cc) = make_float2(acc[mi][ni][2], acc[mi][ni][3]);
        }
    }
}

// ---------------- twiddle table ----------------
__global__ void twiddle_kernel() {
    int k = blockIdx.x * blockDim.x + threadIdx.x;
    if (k < NHALF) {
        float s, c;
        sincospif(2.0f * (float)k / (float)NFFT, &s, &c);
        g_tw[k] = make_float2(c, -s);
    }
}

// ---------------- complex helpers ----------------
__device__ __forceinline__ float2 cmul(float2 a, float2 b) {
    return make_float2(fmaf(a.x, b.x, -a.y * b.y), fmaf(a.x, b.y, a.y * b.x));
}
__device__ __forceinline__ float2 cadd(float2 a, float2 b) { return make_float2(a.x + b.x, a.y + b.y); }
__device__ __forceinline__ float2 csub(float2 a, float2 b) { return make_float2(a.x - b.x, a.y - b.y); }
__device__ __forceinline__ float silu_f(float x) { return x / (1.0f + __expf(-x)); }

// ---------------- FFT 8192: Stockham radix-8 (4 stages) + radix-2, 1024 thr --------
__device__ float2* fft8192_r8(float2* src, float2* dst, const float2* __restrict__ tw,
                              float sgn, int tid, bool padded, bool halfOut)
{
    const float RH = 0.70710678118654752f;

    int s = 1;
    #pragma unroll 1
    for (int st = 0; st < 4; ++st) {
        const int sm1 = s - 1;
        {
            int i  = tid;
            int q  = i & sm1;
            int ps = i - q;

            float2 a0 = src[SKW(i)];
            float2 a1 = src[SKW(i + 1024)];
            float2 a2 = src[SKW(i + 2048)];
            float2 a3 = src[SKW(i + 3072)];

            float2 E0, E1, E2, E3, O0, O1, O2, O3;
            if (padded && st == 0) {
                float2 m2 = make_float2(sgn * a2.y, -sgn * a2.x);
                float2 m3 = make_float2(sgn * a3.y, -sgn * a3.x);
                E0 = cadd(a0, a2); E2 = csub(a0, a2);
                E1 = cadd(a0, m2); E3 = csub(a0, m2);
                O0 = cadd(a1, a3); O2 = csub(a1, a3);
                O1 = cadd(a1, m3); O3 = csub(a1, m3);
            } else {
                float2 a4 = src[SKW(i + 4096)];
                float2 a5 = src[SKW(i + 5120)];
                float2 a6 = src[SKW(i + 6144)];
                float2 a7 = src[SKW(i + 7168)];
                float2 t0 = cadd(a0, a4), t1 = csub(a0, a4);
                float2 t2 = cadd(a2, a6), t3 = csub(a2, a6);
                float2 m3e = make_float2(sgn * t3.y, -sgn * t3.x);
                E0 = cadd(t0, t2); E2 = csub(t0, t2);
                E1 = cadd(t1, m3e); E3 = csub(t1, m3e);
                float2 u0 = cadd(a1, a5), u1 = csub(a1, a5);
                float2 u2 = cadd(a3, a7), u3 = csub(a3, a7);
                float2 m3o = make_float2(sgn * u3.y, -sgn * u3.x);
                O0 = cadd(u0, u2); O2 = csub(u0, u2);
                O1 = cadd(u1, m3o); O3 = csub(u1, m3o);
            }

            float2 W1O = make_float2(RH * (O1.x + sgn * O1.y), RH * (O1.y - sgn * O1.x));
            float2 W2O = make_float2(sgn * O2.y, -sgn * O2.x);
            float2 W3O = make_float2(RH * (sgn * O3.y - O3.x), -RH * (O3.y + sgn * O3.x));

            float2 X0 = cadd(E0, O0),  X4 = csub(E0, O0);
            float2 X1 = cadd(E1, W1O), X5 = csub(E1, W1O);
            float2 X2 = cadd(E2, W2O), X6 = csub(E2, W2O);
            float2 X3 = cadd(E3, W3O), X7 = csub(E3, W3O);

            float2 w1 = tw[ps];     w1.y *= sgn;
            float2 w2 = tw[2 * ps]; w2.y *= sgn;
            float2 w4 = tw[4 * ps]; w4.y *= sgn;
            float2 w3 = cmul(w1, w2);
            float2 w5 = cmul(w1, w4);
            float2 w6 = cmul(w2, w4);
            float2 w7 = cmul(w3, w4);

            int o = q + 8 * ps;
            dst[SKW(o)]         = X0;
            dst[SKW(o + s)]     = cmul(X1, w1);
            dst[SKW(o + 2 * s)] = cmul(X2, w2);
            dst[SKW(o + 3 * s)] = cmul(X3, w3);
            dst[SKW(o + 4 * s)] = cmul(X4, w4);
            dst[SKW(o + 5 * s)] = cmul(X5, w5);
            dst[SKW(o + 6 * s)] = cmul(X6, w6);
            dst[SKW(o + 7 * s)] = cmul(X7, w7);
        }
        __syncthreads();
        float2* t = src; src = dst; dst = t;
        s <<= 3;
    }

    #pragma unroll
    for (int r = 0; r < 4; ++r) {
        int i = tid + r * NTHR;
        float2 a = src[SKW(i)];
        float2 b = src[SKW(i + NHALF)];
        dst[SKW(i)] = cadd(a, b);
        if (!halfOut) dst[SKW(i + NHALF)] = csub(a, b);
    }
    __syncthreads();
    return dst;
}

// ---- FFT 4096: Stockham radix-8, 4 stages, 512 thr, twiddles from GLOBAL g_tw ----
// tw4[x] = g_tw[2x].
__device__ float2* fft4096_r8g(float2* src, float2* dst, float sgn, int tid,
                               bool padded, bool halfOut)
{
    const float RH = 0.70710678118654752f;

    int s = 1;
    #pragma unroll 1
    for (int st = 0; st < 4; ++st) {
        const int sm1 = s - 1;
        {
            int i  = tid;
            int q  = i & sm1;
            int ps = i - q;

            // prefetch twiddles from global (L2-resident) before the butterfly
            float2 w1 = __ldg(&g_tw[2 * ps]);
            float2 w2 = __ldg(&g_tw[4 * ps]);
            float2 w4 = __ldg(&g_tw[8 * ps]);
            w1.y *= sgn; w2.y *= sgn; w4.y *= sgn;

            float2 a0 = src[SKW(i)];
            float2 a1 = src[SKW(i + 512)];
            float2 a2 = src[SKW(i + 1024)];
            float2 a3 = src[SKW(i + 1536)];

            float2 E0, E1, E2, E3, O0, O1, O2, O3;
            if (padded && st == 0) {
                float2 m2 = make_float2(sgn * a2.y, -sgn * a2.x);
                float2 m3 = make_float2(sgn * a3.y, -sgn * a3.x);
                E0 = cadd(a0, a2); E2 = csub(a0, a2);
                E1 = cadd(a0, m2); E3 = csub(a0, m2);
                O0 = cadd(a1, a3); O2 = csub(a1, a3);
                O1 = cadd(a1, m3); O3 = csub(a1, m3);
            } else {
                float2 a4 = src[SKW(i + 2048)];
                float2 a5 = src[SKW(i + 2560)];
                float2 a6 = src[SKW(i + 3072)];
                float2 a7 = src[SKW(i + 3584)];
                float2 t0 = cadd(a0, a4), t1 = csub(a0, a4);
                float2 t2 = cadd(a2, a6), t3 = csub(a2, a6);
                float2 m3e = make_float2(sgn * t3.y, -sgn * t3.x);
                E0 = cadd(t0, t2); E2 = csub(t0, t2);
                E1 = cadd(t1, m3e); E3 = csub(t1, m3e);
                float2 u0 = cadd(a1, a5), u1 = csub(a1, a5);
                float2 u2 = cadd(a3, a7), u3 = csub(a3, a7);
                float2 m3o = make_float2(sgn * u3.y, -sgn * u3.x);
                O0 = cadd(u0, u2); O2 = csub(u0, u2);
                O1 = cadd(u1, m3o); O3 = csub(u1, m3o);
            }

            float2 W1O = make_float2(RH * (O1.x + sgn * O1.y), RH * (O1.y - sgn * O1.x));
            float2 W2O = make_float2(sgn * O2.y, -sgn * O2.x);
            float2 W3O = make_float2(RH * (sgn * O3.y - O3.x), -RH * (O3.y + sgn * O3.x));

            float2 X0 = cadd(E0, O0),  X4 = csub(E0, O0);
            float2 X1 = cadd(E1, W1O), X5 = csub(E1, W1O);
            float2 X2 = cadd(E2, W2O), X6 = csub(E2, W2O);
            float2 X3 = cadd(E3, W3O), X7 = csub(E3, W3O);

            float2 w3 = cmul(w1, w2);

            int o = q + 8 * ps;
            dst[SKW(o)]         = X0;
            dst[SKW(o + s)]     = cmul(X1, w1);
            dst[SKW(o + 2 * s)] = cmul(X2, w2);
            dst[SKW(o + 3 * s)] = cmul(X3, w3);
            if (!(halfOut && st == 3)) {
                float2 w5 = cmul(w1, w4);
                float2 w6 = cmul(w2, w4);
                float2 w7 = cmul(w3, w4);
                dst[SKW(o + 4 * s)] = cmul(X4, w4);
                dst[SKW(o + 5 * s)] = cmul(X5, w5);
                dst[SKW(o + 6 * s)] = cmul(X6, w6);
                dst[SKW(o + 7 * s)] = cmul(X7, w7);
            }
        }
        __syncthreads();
        float2* t = src; src = dst; dst = t;
        s <<= 3;
    }
    return src;
}

// ---------------- kernel spectra: two real channels per 8192 FFT -------------------
#define SMEM_FFTK ((2 * SKWN + NHALF) * (int)sizeof(float2))
__global__ void __launch_bounds__(NTHR) fftk_kernel(const float* __restrict__ k_ssm)
{
    float2* buf0 = (float2*)s4_smem;
    float2* buf1 = buf0 + SKWN;
    float2* tws  = buf1 + SKWN;
    const int h0 = blockIdx.x * 2;
    const int tid = threadIdx.x;

    for (int i = tid; i < NHALF; i += NTHR) tws[i] = g_tw[i];
    const float* k0 = k_ssm + (size_t)h0 * L_SEQ;
    const float* k1 = k0 + L_SEQ;
    for (int l = tid; l < L_SEQ; l += NTHR)
        buf0[SKW(l)] = make_float2(k0[l], k1[l]);
    __syncthreads();

    float2* F = fft8192_r8(buf0, buf1, tws, 1.0f, tid, true, false);

    float2* H0 = g_Hf + (size_t)h0 * NFFT;
    float2* H1 = H0 + NFFT;
    for (int k = tid; k < NFFT; k += NTHR) {
        float2 Fk = F[SKW(k)];
        float2 Fn = F[SKW((NFFT - k) & (NFFT - 1))];
        H0[k] = make_float2(0.5f * (Fk.x + Fn.x), 0.5f * (Fk.y - Fn.y));
        float2 Bd = make_float2(Fk.x - Fn.x, Fk.y + Fn.y);
        H1[k] = make_float2(0.5f * Bd.y, -0.5f * Bd.x);
    }
}

// ------- fused conv: conv4+SiLU -> rFFT(4096) conv -> D_skip -> *SiLU(z) -------
// SMEM = 2 FFT buffers only (68KB) -> 3 CTAs/SM. Twiddles from global; conv+SiLU
// recomputed in the epilogue instead of cached.
#define SMEM_CONV4 (2 * SKWN4 * (int)sizeof(float2))
__global__ void __launch_bounds__(512, 3) convfft_kernel(const float* __restrict__ conv_w,
                                                         const float* __restrict__ conv_b,
                                                         const float* __restrict__ D_skip)
{
    float2* buf0 = (float2*)s4_smem;
    float2* buf1 = buf0 + SKWN4;

    const int bh  = blockIdx.x;
    const int h   = bh >> 1;
    const int b   = bh & 1;
    const int tid = threadIdx.x;

    const float w0 = conv_w[h * 4 + 0];
    const float w1 = conv_w[h * 4 + 1];
    const float w2 = conv_w[h * 4 + 2];
    const float w3 = conv_w[h * 4 + 3];
    const float cb = conv_b[h];

    const __half* gx = g_xzH + ((size_t)(b * EDIM) + h) * L_SEQ;

    for (int n = tid; n < 2048; n += 512) {
        int l0 = 2 * n;
        float x0  = __half2float(gx[l0]);
        float x1  = __half2float(gx[l0 + 1]);
        float a0 = fmaf(w3, x0, cb);
        float a1 = fmaf(w3, x1, cb);
        a1 = fmaf(w2, x0, a1);
        if (l0 >= 1) {
            float xm1 = __half2float(gx[l0 - 1]);
            a0 = fmaf(w2, xm1, a0); a1 = fmaf(w1, xm1, a1);
        }
        if (l0 >= 2) {
            float xm2 = __half2float(gx[l0 - 2]);
            a0 = fmaf(w1, xm2, a0); a1 = fmaf(w0, xm2, a1);
        }
        if (l0 >= 3) {
            float xm3 = __half2float(gx[l0 - 3]);
            a0 = fmaf(w0, xm3, a0);
        }
        buf0[SKW(n)] = make_float2(silu_f(a0), silu_f(a1));
    }
    for (int n = 2048 + tid; n < 4096; n += 512)
        buf0[SKW(n)] = make_float2(0.f, 0.f);
    __syncthreads();

    float2* Z = fft4096_r8g(buf0, buf1, 1.0f, tid, true, false);
    float2* W = (Z == buf0) ? buf1 : buf0;

    // pointwise, paired: thread handles k=n and k'=4096-n (n=0 -> 0 and 2048)
    const float2* __restrict__ Hrow = g_Hf + (size_t)h * NFFT;
    for (int n = tid; n < 2048; n += 512) {
        const int ka = n;
        const int kb = (n == 0) ? 2048 : 4096 - n;
        float2 Za = Z[SKW(ka)];
        float2 Zb = Z[SKW(kb)];
        float2 ta = __ldg(&g_tw[ka]);
        float2 tb = (n == 0) ? __ldg(&g_tw[2048]) : make_float2(-ta.x, ta.y);
        float2 Pa = (n == 0) ? Za : Zb;
        float2 Pb = (n == 0) ? Zb : Za;

        {
            float2 Zc = make_float2(Pa.x, -Pa.y);
            float2 Ze = make_float2(0.5f * (Za.x + Zc.x), 0.5f * (Za.y + Zc.y));
            float2 d  = make_float2(Za.x - Zc.x, Za.y - Zc.y);
            float2 Zo = make_float2(0.5f * d.y, -0.5f * d.x);
            float2 tZo = cmul(ta, Zo);
            float2 Xa = cadd(Ze, tZo);
            float2 Xb = csub(Ze, tZo);
            float2 Ya = cmul(Xa, Hrow[ka]);
            float2 Yb = cmul(Xb, Hrow[ka + 4096]);
            float2 Ye = make_float2(0.5f * (Ya.x + Yb.x), 0.5f * (Ya.y + Yb.y));
            float2 u  = make_float2(0.5f * (Ya.x - Yb.x), 0.5f * (Ya.y - Yb.y));
            float2 tc = make_float2(ta.x, -ta.y);
            float2 Yo = cmul(tc, u);
            W[SKW(ka)] = make_float2(Ye.x - Yo.y, Ye.y + Yo.x);
        }
        {
            float2 Zc = make_float2(Pb.x, -Pb.y);
            float2 Ze = make_float2(0.5f * (Zb.x + Zc.x), 0.5f * (Zb.y + Zc.y));
            float2 d  = make_float2(Zb.x - Zc.x, Zb.y - Zc.y);
            float2 Zo = make_float2(0.5f * d.y, -0.5f * d.x);
            float2 tZo = cmul(tb, Zo);
            float2 Xa = cadd(Ze, tZo);
            float2 Xb = csub(Ze, tZo);
            float2 Ya = cmul(Xa, Hrow[kb]);
            float2 Yb = cmul(Xb, Hrow[kb + 4096]);
            float2 Ye = make_float2(0.5f * (Ya.x + Yb.x), 0.5f * (Ya.y + Yb.y));
            float2 u  = make_float2(0.5f * (Ya.x - Yb.x), 0.5f * (Ya.y - Yb.y));
            float2 tc = make_float2(tb.x, -tb.y);
            float2 Yo = cmul(tc, u);
            W[SKW(kb)] = make_float2(Ye.x - Yo.y, Ye.y + Yo.x);
        }
    }
    __syncthreads();

    float2* other = (W == buf0) ? buf1 : buf0;
    float2* R = fft4096_r8g(W, other, -1.0f, tid, false, true);

    const float dsk = D_skip[h];
    const __half* gz = g_xzH + ((size_t)(b * EDIM) + DINNER + h) * L_SEQ;
    __half*       gy = g_yH + ((size_t)(b * DINNER) + h) * L_SEQ;
    const float invn = 1.0f / 4096.0f;
    for (int n = tid; n < 2048; n += 512) {
        // recompute conv+silu (xs) for positions 2n, 2n+1
        int l0 = 2 * n;
        float x0  = __half2float(gx[l0]);
        float x1  = __half2float(gx[l0 + 1]);
        float a0 = fmaf(w3, x0, cb);
        float a1 = fmaf(w3, x1, cb);
        a1 = fmaf(w2, x0, a1);
        if (l0 >= 1) {
            float xm1 = __half2float(gx[l0 - 1]);
            a0 = fmaf(w2, xm1, a0); a1 = fmaf(w1, xm1, a1);
        }
        if (l0 >= 2) {
            float xm2 = __half2float(gx[l0 - 2]);
            a0 = fmaf(w1, xm2, a0); a1 = fmaf(w0, xm2, a1);
        }
        if (l0 >= 3) {
            float xm3 = __half2float(gx[l0 - 3]);
            a0 = fmaf(w0, xm3, a0);
        }
        float xv0 = silu_f(a0);
        float xv1 = silu_f(a1);

        float2 wv = R[SKW(n)];
        __half2 zh = *(const __half2*)(gz + 2 * n);
        float z0 = __half2float(__low2half(zh));
        float z1 = __half2float(__high2half(zh));
        float y0 = fmaf(wv.x, invn, dsk * xv0);
        float y1 = fmaf(wv.y, invn, dsk * xv1);
        *(__half2*)(gy + 2 * n) = __floats2half2_rn(y0 * silu_f(z0), y1 * silu_f(z1));
    }
}

// ---------------- launch ----------------
extern "C" void kernel_launch(void* const* d_in, const int* in_sizes, int n_in,
                              void* d_out, int out_size)
{
    (void)in_sizes; (void)n_in; (void)out_size;
    const float* hs     = (const float*)d_in[0];
    const float* W_in   = (const float*)d_in[1];
    const float* conv_w = (const float*)d_in[2];
    const float* conv_b = (const float*)d_in[3];
    const float* k_ssm  = (const float*)d_in[4];
    const float* D_skip = (const float*)d_in[5];
    const float* W_out  = (const float*)d_in[6];
    float* out = (float*)d_out;

    cudaFuncSetAttribute(fftk_kernel,    cudaFuncAttributeMaxDynamicSharedMemorySize, SMEM_FFTK);
    cudaFuncSetAttribute(convfft_kernel, cudaFuncAttributeMaxDynamicSharedMemorySize, SMEM_CONV4);

    __half* xzH  = nullptr; cudaGetSymbolAddress((void**)&xzH, g_xzH);
    __half* hsH  = nullptr; cudaGetSymbolAddress((void**)&hsH, g_hsH);
    __half* winH = nullptr; cudaGetSymbolAddress((void**)&winH, g_WinH);
    __half* woutH= nullptr; cudaGetSymbolAddress((void**)&woutH, g_WoutH);
    __half* yH   = nullptr; cudaGetSymbolAddress((void**)&yH, g_yH);

    // fork a side stream for the fftk chain (independent of GEMM1)
    cudaStream_t sB;
    cudaStreamCreateWithFlags(&sB, cudaStreamNonBlocking);
    cudaEvent_t eFork, eJoin;
    cudaEventCreateWithFlags(&eFork, cudaEventDisableTiming);
    cudaEventCreateWithFlags(&eJoin, cudaEventDisableTiming);

    cudaEventRecord(eFork, 0);
    cudaStreamWaitEvent(sB, eFork, 0);

    // ---- stream B: twiddle -> f2h(W_out) -> fftk ----
    twiddle_kernel<<<NHALF / 512, 512, 0, sB>>>();
    {
        long long n4 = (long long)DMODEL * DINNER / 4;
        f2h_kernel<<<(unsigned)((n4 + 255) / 256), 256, 0, sB>>>(W_out, woutH, n4);
    }
    fftk_kernel<<<DINNER / 2, NTHR, SMEM_FFTK, sB>>>(k_ssm);
    cudaEventRecord(eJoin, sB);

    // ---- main stream: f2h(hs, W_in) -> GEMM1 ----
    {
        long long n4;
        n4 = (long long)BATCH * L_SEQ * DMODEL / 4;
        f2h_kernel<<<(unsigned)((n4 + 255) / 256), 256>>>(hs, hsH, n4);
        n4 = (long long)EDIM * DMODEL / 4;
        f2h_kernel<<<(unsigned)((n4 + 255) / 256), 256>>>(W_in, winH, n4);
    }
    gemm_mma_h<<<dim3(L_SEQ / 128, EDIM / 128, BATCH), 256>>>(
        winH, hsH, xzH, DMODEL, DMODEL, L_SEQ, DMODEL,
        0LL, (long long)L_SEQ * DMODEL, (long long)EDIM * L_SEQ);

    // join, then the dependent tail
    cudaStreamWaitEvent(0, eJoin, 0);
    convfft_kernel<<<BATCH * DINNER, 512, SMEM_CONV4>>>(conv_w, conv_b, D_skip);
    gemm2_nn<<<dim3(DMODEL / 128, L_SEQ / 128, BATCH), 256>>>(yH, woutH, out);
    // stream/events intentionally not destroyed (stream-capture safe; host-side only)
}